// round 1
// baseline (speedup 1.0000x reference)
#include <cuda_runtime.h>
#include <cuda_bf16.h>

#define LOG_2PI 1.8378770664093453f

// out[i][j] = coef_i * exp( inv2s * (2*dot(nuc_i, sb_j) - ||sb_j||^2) ) + lc_i * chi[j]
// where coef_i = eps[i]*eps_perm[i]*rho * exp(-LOG_2PI - log(sigma) - ||nuc_i||^2 * inv2s)
//       lc_i   = eps[i]*d_drop[i]
//       inv2s  = 1/(2*sigma)
__global__ void __launch_bounds__(256)
infer_positions_kernel(const float2* __restrict__ nuc,     // [N]
                       const float2* __restrict__ sb,      // [M]
                       const float*  __restrict__ eperm,   // [N]
                       const float*  __restrict__ eps,     // [N]
                       const float*  __restrict__ ddrop,   // [N]
                       const float*  __restrict__ rho,     // [1]
                       const float*  __restrict__ sigma,   // [1]
                       const float*  __restrict__ chi,     // [M]
                       float* __restrict__ out,
                       int M)
{
    const int row  = blockIdx.y;
    const int col0 = (blockIdx.x * blockDim.x + threadIdx.x) * 4;
    if (col0 >= M) return;

    const float2 n   = __ldg(&nuc[row]);
    const float  sig = __ldg(&sigma[0]);
    const float  inv2s = 0.5f / sig;
    const float  sq_n  = n.x * n.x + n.y * n.y;
    const float  e     = __ldg(&eps[row]);
    const float  coef  = e * __ldg(&eperm[row]) * __ldg(&rho[0]) *
                         __expf(-LOG_2PI - __logf(sig) - sq_n * inv2s);
    const float  lc    = e * __ldg(&ddrop[row]);

    // precompute scaled row vector so the exponent is 2 FMAs + 1 mul
    const float nx2 = 2.0f * n.x * inv2s;
    const float ny2 = 2.0f * n.y * inv2s;

    const float4 c  = *reinterpret_cast<const float4*>(chi + col0);
    const float4 sA = *reinterpret_cast<const float4*>(&sb[col0]);      // s0.xy, s1.xy
    const float4 sB = *reinterpret_cast<const float4*>(&sb[col0 + 2]);  // s2.xy, s3.xy

    float4 r;
    {
        float sx = sA.x, sy = sA.y;
        float arg = fmaf(nx2, sx, fmaf(ny2, sy, -(sx * sx + sy * sy) * inv2s));
        r.x = fmaf(lc, c.x, coef * __expf(arg));
    }
    {
        float sx = sA.z, sy = sA.w;
        float arg = fmaf(nx2, sx, fmaf(ny2, sy, -(sx * sx + sy * sy) * inv2s));
        r.y = fmaf(lc, c.y, coef * __expf(arg));
    }
    {
        float sx = sB.x, sy = sB.y;
        float arg = fmaf(nx2, sx, fmaf(ny2, sy, -(sx * sx + sy * sy) * inv2s));
        r.z = fmaf(lc, c.z, coef * __expf(arg));
    }
    {
        float sx = sB.z, sy = sB.w;
        float arg = fmaf(nx2, sx, fmaf(ny2, sy, -(sx * sx + sy * sy) * inv2s));
        r.w = fmaf(lc, c.w, coef * __expf(arg));
    }

    // streaming store: output is write-once, 128 MB, keep it out of L2 residency
    __stcs(reinterpret_cast<float4*>(out + (size_t)row * M + col0), r);
}

extern "C" void kernel_launch(void* const* d_in, const int* in_sizes, int n_in,
                              void* d_out, int out_size)
{
    const float2* nuc   = (const float2*)d_in[0];   // nuc_locations [N,2]
    const float2* sb    = (const float2*)d_in[1];   // SB_locations  [M,2]
    const float*  eperm = (const float*)d_in[2];    // epsilon_perm  [N]
    const float*  eps   = (const float*)d_in[3];    // epsilon       [N]
    const float*  ddrop = (const float*)d_in[4];    // d_drop        [N]
    const float*  rho   = (const float*)d_in[5];    // rho_SB        [1]
    const float*  sigma = (const float*)d_in[6];    // sigma_SB      [1]
    const float*  chi   = (const float*)d_in[7];    // chi_ambient   [M]
    float* out = (float*)d_out;

    const int N = in_sizes[0] / 2;
    const int M = in_sizes[1] / 2;

    const int threads = 256;
    const int cols_per_block = threads * 4;
    dim3 grid((M + cols_per_block - 1) / cols_per_block, N);
    infer_positions_kernel<<<grid, threads>>>(nuc, sb, eperm, eps, ddrop,
                                              rho, sigma, chi, out, M);
}

// round 4
// speedup vs baseline: 1.6902x; 1.6902x over previous
#include <cuda_runtime.h>
#include <cuda_bf16.h>

#define LOG_2PI 1.8378770664093453f
#define ROWS 16
#define THREADS 256
#define COLS_PER_BLOCK (THREADS * 4)

// out[i][j] = coef_i * exp( nx2_i*sx_j + ny2_i*sy_j + c_j ) + lc_i * chi[j]
//   c_j    = -(sx^2+sy^2) * inv2s              (per column, computed once)
//   nx2_i  = 2*nx*inv2s,  ny2_i = 2*ny*inv2s   (per row, computed once)
//   coef_i = eps*eperm*rho * exp(-LOG_2PI - log(sigma) - ||nuc||^2 * inv2s)
//   lc_i   = eps*d_drop
__global__ void __launch_bounds__(THREADS)
infer_positions_kernel(const float2* __restrict__ nuc,     // [N]
                       const float2* __restrict__ sb,      // [M]
                       const float*  __restrict__ eperm,   // [N]
                       const float*  __restrict__ eps,     // [N]
                       const float*  __restrict__ ddrop,   // [N]
                       const float*  __restrict__ rho,     // [1]
                       const float*  __restrict__ sigma,   // [1]
                       const float*  __restrict__ chi,     // [M]
                       float* __restrict__ out,
                       int M)
{
    __shared__ float4 rp[ROWS];   // {nx2, ny2, coef, lc} per row of this tile

    const int row0 = blockIdx.y * ROWS;
    const int col0 = blockIdx.x * COLS_PER_BLOCK + threadIdx.x * 4;

    const float sig   = __ldg(&sigma[0]);
    const float inv2s = 0.5f / sig;

    // 16 threads compute the per-row parameters for this tile
    if (threadIdx.x < ROWS) {
        const int row = row0 + threadIdx.x;
        const float2 n = __ldg(&nuc[row]);
        const float  e = __ldg(&eps[row]);
        const float sq_n = n.x * n.x + n.y * n.y;
        float4 p;
        p.x = 2.0f * n.x * inv2s;
        p.y = 2.0f * n.y * inv2s;
        p.z = e * __ldg(&eperm[row]) * __ldg(&rho[0]) *
              __expf(-LOG_2PI - __logf(sig) - sq_n * inv2s);
        p.w = e * __ldg(&ddrop[row]);
        rp[threadIdx.x] = p;
    }

    // Per-column data: loaded ONCE, reused for all ROWS rows
    const float4 c  = *reinterpret_cast<const float4*>(chi + col0);
    const float4 sA = *reinterpret_cast<const float4*>(&sb[col0]);      // s0,s1
    const float4 sB = *reinterpret_cast<const float4*>(&sb[col0 + 2]);  // s2,s3

    const float c0 = -(sA.x * sA.x + sA.y * sA.y) * inv2s;
    const float c1 = -(sA.z * sA.z + sA.w * sA.w) * inv2s;
    const float c2 = -(sB.x * sB.x + sB.y * sB.y) * inv2s;
    const float c3 = -(sB.z * sB.z + sB.w * sB.w) * inv2s;

    __syncthreads();

    float* optr = out + (size_t)row0 * M + col0;

    #pragma unroll 4
    for (int r = 0; r < ROWS; r++) {
        const float4 p = rp[r];   // broadcast LDS.128

        float4 o;
        o.x = fmaf(p.w, c.x, p.z * __expf(fmaf(p.x, sA.x, fmaf(p.y, sA.y, c0))));
        o.y = fmaf(p.w, c.y, p.z * __expf(fmaf(p.x, sA.z, fmaf(p.y, sA.w, c1))));
        o.z = fmaf(p.w, c.z, p.z * __expf(fmaf(p.x, sB.x, fmaf(p.y, sB.y, c2))));
        o.w = fmaf(p.w, c.w, p.z * __expf(fmaf(p.x, sB.z, fmaf(p.y, sB.w, c3))));

        __stcs(reinterpret_cast<float4*>(optr), o);
        optr += M;
    }
}

extern "C" void kernel_launch(void* const* d_in, const int* in_sizes, int n_in,
                              void* d_out, int out_size)
{
    const float2* nuc   = (const float2*)d_in[0];
    const float2* sb    = (const float2*)d_in[1];
    const float*  eperm = (const float*)d_in[2];
    const float*  eps   = (const float*)d_in[3];
    const float*  ddrop = (const float*)d_in[4];
    const float*  rho   = (const float*)d_in[5];
    const float*  sigma = (const float*)d_in[6];
    const float*  chi   = (const float*)d_in[7];
    float* out = (float*)d_out;

    const int N = in_sizes[0] / 2;   // 8192
    const int M = in_sizes[1] / 2;   // 4096

    dim3 grid((M + COLS_PER_BLOCK - 1) / COLS_PER_BLOCK, (N + ROWS - 1) / ROWS);
    infer_positions_kernel<<<grid, THREADS>>>(nuc, sb, eperm, eps, ddrop,
                                              rho, sigma, chi, out, M);
}